// round 2
// baseline (speedup 1.0000x reference)
#include <cuda_runtime.h>
#include <math.h>

// Van Rossum distance:
//   diff = input - target            [1024, 16384] f32
//   y[t] = d*y[t-1] + diff[t]        d = exp(-1/20), per row
//   out  = sqrt( sum(y^2) / 20 )     scalar f32
//
// Strategy: blocked parallel scan of the first-order recurrence.
//   - 1 block per row, 256 threads, 64 contiguous elements per thread.
//   - Per thread, one streaming pass computes A = sum(y_loc^2),
//     B = sum(y_loc * d^(k+1)), C = sum(d^(2(k+1))), and local carry c_loc,
//     where y_loc is the chunk scan with zero carry-in.
//   - Warp-shuffle weighted scan (weight D = d^64) + cross-warp chain gives
//     each thread its true carry-in c; chunk contribution = A + 2cB + c^2 C.
//   - Deterministic block reduce -> g_partials[row]; second kernel reduces
//     1024 partials and writes sqrt(sum * 0.05).

#define LEN      16384
#define NROWS    1024
#define THREADS  256
#define CHUNK    64          // LEN / THREADS
#define VECS     (CHUNK / 4) // 16 float4 loads per array per thread

__device__ float g_partials[NROWS];

__global__ __launch_bounds__(THREADS) void vr_scan_kernel(
    const float* __restrict__ inp, const float* __restrict__ tgt)
{
    const int row  = blockIdx.x;
    const int tid  = threadIdx.x;
    const int lane = tid & 31;
    const int warp = tid >> 5;

    const float d  = 0.951229424500714f;   // exp(-1/20)
    const float d2 = d * d;

    // D = d^64 via repeated squaring (exact-ish, 6 mults)
    float D = d;
    #pragma unroll
    for (int i = 0; i < 6; i++) D = D * D;   // d^2,4,8,16,32,64
    // C = sum_{k=1..64} d^(2k) = d2*(1 - (D*D)) / (1 - d2)   [D*D = d^128 = d2^64]
    const float Cc = d2 * (1.0f - D * D) / (1.0f - d2);

    const size_t base = (size_t)row * LEN + (size_t)tid * CHUNK;
    const float4* __restrict__ ip = (const float4*)(inp + base);
    const float4* __restrict__ tp = (const float4*)(tgt + base);

    float y  = 0.0f;   // local scan value (zero carry-in)
    float A  = 0.0f;   // sum y_loc^2
    float Bc = 0.0f;   // sum y_loc * d^(k+1)
    float pk = d;      // d^(k+1), k = 0..63

    #pragma unroll
    for (int j = 0; j < VECS; j++) {
        float4 a = ip[j];
        float4 b = tp[j];
        float xs0 = a.x - b.x;
        float xs1 = a.y - b.y;
        float xs2 = a.z - b.z;
        float xs3 = a.w - b.w;

        y = fmaf(d, y, xs0); A = fmaf(y, y, A); Bc = fmaf(y, pk, Bc); pk *= d;
        y = fmaf(d, y, xs1); A = fmaf(y, y, A); Bc = fmaf(y, pk, Bc); pk *= d;
        y = fmaf(d, y, xs2); A = fmaf(y, y, A); Bc = fmaf(y, pk, Bc); pk *= d;
        y = fmaf(d, y, xs3); A = fmaf(y, y, A); Bc = fmaf(y, pk, Bc); pk *= d;
    }
    // y == c_loc: chunk-final value with zero carry-in.

    // ---- weighted inclusive scan across the warp: S_t = sum_{j<=t} c_j * D^(t-j)
    float s = y;
    float w = D;                    // D^(2^step)
    #pragma unroll
    for (int off = 1; off < 32; off <<= 1) {
        float up = __shfl_up_sync(0xffffffffu, s, off);
        if (lane >= off) s = fmaf(w, up, s);
        w *= w;
    }
    const float D32 = w;            // after 5 squarings from D: D^32 = d^2048

    // ---- cross-warp chain (8 warps)
    __shared__ float warpTot[8];
    __shared__ float warpCarry[8];
    if (lane == 31) warpTot[warp] = s;
    __syncthreads();
    if (tid == 0) {
        float g = 0.0f;
        #pragma unroll
        for (int v = 0; v < 8; v++) {
            warpCarry[v] = g;                    // carry into warp v
            g = fmaf(D32, g, warpTot[v]);        // global S at end of warp v
        }
    }
    __syncthreads();

    // exclusive local scan value
    float E = __shfl_up_sync(0xffffffffu, s, 1);
    if (lane == 0) E = 0.0f;

    // D^lane via lane bits (5 mults)
    float Dlane = 1.0f;
    float bsq   = D;
    #pragma unroll
    for (int b = 0; b < 5; b++) {
        if (lane & (1 << b)) Dlane *= bsq;
        bsq *= bsq;
    }
    // carry into this thread's chunk
    const float c = fmaf(Dlane, warpCarry[warp], E);

    // chunk contribution: A + 2cB + c^2 C
    float contrib = fmaf(c, fmaf(c, Cc, 2.0f * Bc), A);

    // ---- deterministic block reduce (shuffle within warp, smem across warps)
    #pragma unroll
    for (int off = 16; off > 0; off >>= 1)
        contrib += __shfl_down_sync(0xffffffffu, contrib, off);

    __shared__ float wsum[8];
    if (lane == 0) wsum[warp] = contrib;
    __syncthreads();
    if (warp == 0) {
        float v = (lane < 8) ? wsum[lane] : 0.0f;
        #pragma unroll
        for (int off = 4; off > 0; off >>= 1)
            v += __shfl_down_sync(0xffffffffu, v, off);
        if (lane == 0) g_partials[row] = v;
    }
}

__global__ __launch_bounds__(256) void vr_reduce_kernel(float* __restrict__ out)
{
    const int tid  = threadIdx.x;
    const int lane = tid & 31;
    const int warp = tid >> 5;

    float v = 0.0f;
    #pragma unroll
    for (int j = 0; j < NROWS / 256; j++)
        v += g_partials[tid + j * 256];

    #pragma unroll
    for (int off = 16; off > 0; off >>= 1)
        v += __shfl_down_sync(0xffffffffu, v, off);

    __shared__ float wsum[8];
    if (lane == 0) wsum[warp] = v;
    __syncthreads();
    if (warp == 0) {
        float t = (lane < 8) ? wsum[lane] : 0.0f;
        #pragma unroll
        for (int off = 4; off > 0; off >>= 1)
            t += __shfl_down_sync(0xffffffffu, t, off);
        if (lane == 0) out[0] = sqrtf(t * 0.05f);   // sqrt(sum / TAU * DT)
    }
}

extern "C" void kernel_launch(void* const* d_in, const int* in_sizes, int n_in,
                              void* d_out, int out_size)
{
    const float* inp = (const float*)d_in[0];
    const float* tgt = (const float*)d_in[1];
    float* out = (float*)d_out;

    vr_scan_kernel<<<NROWS, THREADS>>>(inp, tgt);
    vr_reduce_kernel<<<1, 256>>>(out);
}

// round 4
// speedup vs baseline: 1.2353x; 1.2353x over previous
#include <cuda_runtime.h>
#include <math.h>

// Van Rossum distance, single-kernel blocked-scan version.
//   diff = input - target            [1024, 16384] f32
//   y[t] = d*y[t-1] + diff[t]        d = exp(-1/20), per row
//   out  = sqrt( sum(y^2) / 20 )     scalar f32
//
// - Stage rows through shared memory in 4 tiles of 4096 floats so global
//   loads are warp-coalesced float4 (4 L1 lines/instr instead of 32).
//   Padded smem layout p = e + e/16 makes per-thread 16-element reads
//   bank-conflict-free (stride 17, gcd(17,32)=1).
// - Carry across stages held in tid0's register, fed into the per-stage
//   8-warp chain. Chunk contribution: A + 2cB + c^2*C16.
// - Fused final reduction via deterministic last-block pattern (int
//   atomic ticket, fixed-order sum) — removes the second kernel launch.

#define LEN      16384
#define NROWS    1024
#define THREADS  256
#define STAGE    4096                 // elements per smem tile
#define NSTAGES  (LEN / STAGE)        // 4
#define SUB      (STAGE / THREADS)    // 16 elements per thread per stage
#define TILE_PAD (STAGE + STAGE / 16) // 4352 floats (pad 1 per 16)

__device__ float        g_partials[NROWS];
__device__ unsigned int g_ticket = 0;

__global__ __launch_bounds__(THREADS) void vr_kernel(
    const float* __restrict__ inp, const float* __restrict__ tgt,
    float* __restrict__ out)
{
    __shared__ float tile[TILE_PAD];
    __shared__ float warpTot[8];
    __shared__ float warpCarry[8];
    __shared__ float wsum[8];
    __shared__ bool  isLast;

    const int row  = blockIdx.x;
    const int tid  = threadIdx.x;
    const int lane = tid & 31;
    const int warp = tid >> 5;

    // ---- constants (runtime, cheap, float) ----
    const float d  = 0.951229424500714f;     // exp(-1/20)
    const float d2 = d * d;
    float D16 = d;                           // d^16 via 4 squarings
    #pragma unroll
    for (int i = 0; i < 4; i++) D16 = D16 * D16;
    float d2_16 = d2;                        // d2^16
    #pragma unroll
    for (int i = 0; i < 4; i++) d2_16 = d2_16 * d2_16;
    const float C16 = d2 * (1.0f - d2_16) / (1.0f - d2);  // sum_{k=1..16} d^2k
    float D512 = D16;                        // D16^32 = d^512
    #pragma unroll
    for (int i = 0; i < 5; i++) D512 = D512 * D512;
    // Dlane = D16^lane (per-thread constant)
    float Dlane = 1.0f, bsq = D16;
    #pragma unroll
    for (int b = 0; b < 5; b++) {
        if (lane & (1 << b)) Dlane *= bsq;
        bsq *= bsq;
    }

    const float4* __restrict__ ip = (const float4*)(inp + (size_t)row * LEN);
    const float4* __restrict__ tp = (const float4*)(tgt + (size_t)row * LEN);

    float contrib = 0.0f;   // this thread's accumulated sum(y^2) share
    float stage_g = 0.0f;   // tid0 only: scan value entering current stage

    #pragma unroll
    for (int s = 0; s < NSTAGES; s++) {
        // -- coalesced load + diff -> padded smem tile --
        #pragma unroll
        for (int j = 0; j < STAGE / (THREADS * 4); j++) {
            const int v = j * THREADS + tid;            // float4 idx in stage
            float4 a = ip[s * (STAGE / 4) + v];
            float4 b = tp[s * (STAGE / 4) + v];
            const int e = v * 4;                        // e%16 in {0,4,8,12}
            const int p = e + (e >> 4);                 // pad stays constant over 4
            tile[p + 0] = a.x - b.x;
            tile[p + 1] = a.y - b.y;
            tile[p + 2] = a.z - b.z;
            tile[p + 3] = a.w - b.w;
        }
        __syncthreads();

        // -- per-thread local scan of 16 contiguous elements (zero carry-in) --
        float y = 0.0f, A = 0.0f, B = 0.0f, pk = d;
        const int base = tid * 17;                      // conflict-free stride
        #pragma unroll
        for (int k = 0; k < SUB; k++) {
            float x = tile[base + k];
            y = fmaf(d, y, x);
            A = fmaf(y, y, A);
            B = fmaf(y, pk, B);
            pk *= d;
        }

        // -- warp weighted inclusive scan of chunk finals (weight D16) --
        float sI = y;
        float w  = D16;
        #pragma unroll
        for (int off = 1; off < 32; off <<= 1) {
            float up = __shfl_up_sync(0xffffffffu, sI, off);
            if (lane >= off) sI = fmaf(w, up, sI);
            w *= w;
        }
        if (lane == 31) warpTot[warp] = sI;
        __syncthreads();

        // -- cross-warp chain incl. stage carry (tid0 serial, 8 steps) --
        if (tid == 0) {
            float g = stage_g;
            #pragma unroll
            for (int v2 = 0; v2 < 8; v2++) {
                warpCarry[v2] = g;
                g = fmaf(D512, g, warpTot[v2]);
            }
            stage_g = g;                                // carry into next stage
        }
        __syncthreads();

        // -- true carry into this thread's 16-chunk --
        float E = __shfl_up_sync(0xffffffffu, sI, 1);
        if (lane == 0) E = 0.0f;
        const float c = fmaf(Dlane, warpCarry[warp], E);

        // chunk contribution: A + 2cB + c^2 C16
        contrib += fmaf(c, fmaf(c, C16, 2.0f * B), A);
        __syncthreads();   // tile reuse guard for next stage
    }

    // ---- deterministic block reduce ----
    #pragma unroll
    for (int off = 16; off > 0; off >>= 1)
        contrib += __shfl_down_sync(0xffffffffu, contrib, off);
    if (lane == 0) wsum[warp] = contrib;
    __syncthreads();
    if (warp == 0) {
        float v = (lane < 8) ? wsum[lane] : 0.0f;
        #pragma unroll
        for (int off = 4; off > 0; off >>= 1)
            v += __shfl_down_sync(0xffffffffu, v, off);
        if (lane == 0) {
            g_partials[row] = v;
            __threadfence();
            unsigned int t = atomicAdd(&g_ticket, 1u);
            isLast = (t == NROWS - 1);
        }
    }
    __syncthreads();

    // ---- last block: fixed-order global reduce (deterministic) ----
    if (isLast) {
        __threadfence();
        float v = 0.0f;
        #pragma unroll
        for (int j = 0; j < NROWS / THREADS; j++)
            v += ((volatile float*)g_partials)[tid + j * THREADS];

        #pragma unroll
        for (int off = 16; off > 0; off >>= 1)
            v += __shfl_down_sync(0xffffffffu, v, off);
        if (lane == 0) wsum[warp] = v;
        __syncthreads();
        if (warp == 0) {
            float t2 = (lane < 8) ? wsum[lane] : 0.0f;
            #pragma unroll
            for (int off = 4; off > 0; off >>= 1)
                t2 += __shfl_down_sync(0xffffffffu, t2, off);
            if (lane == 0) {
                out[0] = sqrtf(t2 * 0.05f);   // sqrt(sum / TAU * DT)
                g_ticket = 0;                 // reset for next graph replay
            }
        }
    }
}

extern "C" void kernel_launch(void* const* d_in, const int* in_sizes, int n_in,
                              void* d_out, int out_size)
{
    const float* inp = (const float*)d_in[0];
    const float* tgt = (const float*)d_in[1];
    float* out = (float*)d_out;

    vr_kernel<<<NROWS, THREADS>>>(inp, tgt, out);
}